// round 14
// baseline (speedup 1.0000x reference)
#include <cuda_runtime.h>
#include <cuda_bf16.h>
#include <cstdint>

static constexpr int Bsz   = 2048;
static constexpr int T     = 512;
static constexpr int CHK   = 8;          // timesteps per ring chunk
static constexpr int NCHK  = T / CHK;    // 64
static constexpr int NSLOT = 16;         // 2 chunks resident
static constexpr int LP    = 20;         // f32 per lane per slot (16 used; bank spread)

// pre-packed Wx B-fragments (bf16 hi/lo), built by prep kernel
__device__ uint2 g_Bh[4][8][32];
__device__ uint2 g_Bl[4][8][32];

// ---------------- helpers ----------------
__device__ __forceinline__ float fast_sigmoid(float x) {
    float e, r;
    asm("ex2.approx.f32 %0, %1;" : "=f"(e) : "f"(x * -1.4426950408889634f));
    asm("rcp.approx.f32 %0, %1;" : "=f"(r) : "f"(1.0f + e));
    return r;
}
__device__ __forceinline__ uint32_t bf16x2_hi(float x0, float x1) {
    uint32_t r; asm("cvt.rn.bf16x2.f32 %0, %1, %2;" : "=r"(r) : "f"(x1), "f"(x0)); return r;
}
__device__ __forceinline__ uint32_t bf16x2_lo(float x0, float x1, uint32_t hi) {
    float h0 = __uint_as_float(hi << 16);
    float h1 = __uint_as_float(hi & 0xFFFF0000u);
    return bf16x2_hi(x0 - h0, x1 - h1);
}
__device__ __forceinline__ void mma16816(float* c, const uint32_t* a, const uint32_t* b) {
    asm("mma.sync.aligned.m16n8k16.row.col.f32.bf16.bf16.f32 "
        "{%0,%1,%2,%3}, {%4,%5,%6,%7}, {%8,%9}, {%0,%1,%2,%3};"
        : "+f"(c[0]), "+f"(c[1]), "+f"(c[2]), "+f"(c[3])
        : "r"(a[0]), "r"(a[1]), "r"(a[2]), "r"(a[3]), "r"(b[0]), "r"(b[1]));
}
#define BARRIER() asm volatile("bar.sync 0, 128;" ::: "memory")

// ============================================================================
// prep: pack Wx into bf16 hi/lo B-fragments (m16n8k16 col-major)
// ============================================================================
__global__ void prep_kernel(const float* __restrict__ Wx) {
    const int tid  = threadIdx.x;
    const int ks   = tid >> 5;
    const int lane = tid & 31;
    const int gr   = lane >> 2;
    const int tq   = (lane & 3) * 2;
    const int k0   = ks * 16 + tq;
#pragma unroll
    for (int nt = 0; nt < 8; nt++) {
        const int n = nt * 8 + gr;
        float w00 = Wx[(k0)     * 64 + n], w01 = Wx[(k0 + 1) * 64 + n];
        float w10 = Wx[(k0 + 8) * 64 + n], w11 = Wx[(k0 + 9) * 64 + n];
        uint32_t h0 = bf16x2_hi(w00, w01);
        uint32_t h1 = bf16x2_hi(w10, w11);
        g_Bh[ks][nt][lane] = make_uint2(h0, h1);
        g_Bl[ks][nt][lane] = make_uint2(bf16x2_lo(w00, w01, h0), bf16x2_lo(w10, w11, h1));
    }
}

// ============================================================================
// Fused warp-specialized LSTM: 1 CTA = 8 batches (bg). Warps 0-2 produce
// z = x*Wx + b into a 16-slot smem ring (m16 tiles = 8 batches x 2 steps);
// warp 3 consumes: MMA recurrence (h*Wh via m16n8k16, D-frag == next A-frag).
// ============================================================================
__global__ void __launch_bounds__(128)
lstm_ws(const float* __restrict__ x,
        const float* __restrict__ Wh,   // [16, 64]
        const float* __restrict__ bias, // [64]
        const float* __restrict__ W2, const float* __restrict__ b2,
        const float* __restrict__ W3, const float* __restrict__ b3,
        const float* __restrict__ Wo, const float* __restrict__ bo,
        float* __restrict__ out)
{
    const int lane = threadIdx.x & 31;
    const int w    = threadIdx.x >> 5;
    const int gr   = lane >> 2;          // 0..7  (frag row group / batch)
    const int tq   = (lane & 3) * 2;     // 0,2,4,6 (frag col pair)
    const int bg   = blockIdx.x;         // batch group (8 batches)

    __shared__ float zbuf[NSLOT][32][LP];    // 40 KB ring of z fragments
    __shared__ float hbuf[8][16];            // final h for MLP tail

    if (w < 3) {
        // ================= PRODUCER =================
        float bs0[8], bs1[8];
#pragma unroll
        for (int nt = 0; nt < 8; nt++) {
            bs0[nt] = __ldg(&bias[nt * 8 + tq]);
            bs1[nt] = __ldg(&bias[nt * 8 + tq + 1]);
        }
        const float* xb = x + (size_t)(bg * 8 + gr) * T * 64;   // this lane's batch row

        // one m16 tile: rows 0..7 = batches @ t0, rows 8..15 = batches @ t0+1
        auto produce_pair = [&](int t0) {
            float2 ar[4][4];
#pragma unroll
            for (int ks = 0; ks < 4; ks++) {
                const int k0 = ks * 16 + tq;
                ar[ks][0] = *(const float2*)(xb + (size_t)(t0)     * 64 + k0);
                ar[ks][1] = *(const float2*)(xb + (size_t)(t0 + 1) * 64 + k0);
                ar[ks][2] = *(const float2*)(xb + (size_t)(t0)     * 64 + k0 + 8);
                ar[ks][3] = *(const float2*)(xb + (size_t)(t0 + 1) * 64 + k0 + 8);
            }
            uint32_t ah[4][4], al[4][4];
#pragma unroll
            for (int ks = 0; ks < 4; ks++)
#pragma unroll
                for (int j = 0; j < 4; j++) {
                    ah[ks][j] = bf16x2_hi(ar[ks][j].x, ar[ks][j].y);
                    al[ks][j] = bf16x2_lo(ar[ks][j].x, ar[ks][j].y, ah[ks][j]);
                }
            float zt[8][4];
#pragma unroll
            for (int nt = 0; nt < 8; nt++)
#pragma unroll
                for (int e = 0; e < 4; e++) zt[nt][e] = 0.0f;
#pragma unroll
            for (int ks = 0; ks < 4; ks++)
#pragma unroll
                for (int nt = 0; nt < 8; nt++) {
                    uint2 bh = __ldg(&g_Bh[ks][nt][lane]);
                    uint2 bl = __ldg(&g_Bl[ks][nt][lane]);
                    mma16816(zt[nt], ah[ks], &bh.x);
                    mma16816(zt[nt], ah[ks], &bl.x);
                    mma16816(zt[nt], al[ks], &bh.x);
                }
            const int s0 = t0 & (NSLOT - 1), s1 = (t0 + 1) & (NSLOT - 1);
#pragma unroll
            for (int nt = 0; nt < 8; nt++) {
                *(float2*)&zbuf[s0][lane][2 * nt] =
                    make_float2(zt[nt][0] + bs0[nt], zt[nt][1] + bs1[nt]);
                *(float2*)&zbuf[s1][lane][2 * nt] =
                    make_float2(zt[nt][2] + bs0[nt], zt[nt][3] + bs1[nt]);
            }
        };

        // prologue: chunk 0 (t = 0..7), 4 t-pairs split over 3 warps
#pragma unroll
        for (int p = 0; p < 4; p++)
            if (p % 3 == w) produce_pair(2 * p);
        BARRIER();
#pragma unroll 1
        for (int k = 0; k < NCHK; k++) {
            if (k + 1 < NCHK) {
#pragma unroll
                for (int p = 0; p < 4; p++)
                    if (p % 3 == w) produce_pair((k + 1) * CHK + 2 * p);
            }
            BARRIER();
        }
    } else {
        // ================= CONSUMER =================
        // Wh B-fragments (hi/lo): b0 = {Wh[tq][n], Wh[tq+1][n]}, b1 = {+8,+9}
        uint32_t bh[8][2], bl[8][2];
#pragma unroll
        for (int nt = 0; nt < 8; nt++) {
            const int n = nt * 8 + gr;
            float w0 = __ldg(&Wh[(tq)     * 64 + n]);
            float w1 = __ldg(&Wh[(tq + 1) * 64 + n]);
            float w2 = __ldg(&Wh[(tq + 8) * 64 + n]);
            float w3 = __ldg(&Wh[(tq + 9) * 64 + n]);
            bh[nt][0] = bf16x2_hi(w0, w1);
            bl[nt][0] = bf16x2_lo(w0, w1, bh[nt][0]);
            bh[nt][1] = bf16x2_hi(w2, w3);
            bl[nt][1] = bf16x2_lo(w2, w3, bh[nt][1]);
        }
        float c0 = 0.0f, c1 = 0.0f, c2 = 0.0f, c3 = 0.0f;
        uint32_t ah0 = 0, ah2 = 0, al0 = 0, al2 = 0;   // h = 0 -> bf16 zeros

        BARRIER();   // matches producer prologue barrier
        float h0v = 0.0f, h1v = 0.0f, h2v = 0.0f, h3v = 0.0f;

#pragma unroll 1
        for (int k = 0; k < NCHK; k++) {
#pragma unroll
            for (int tl = 0; tl < CHK; tl++) {
                const int s = (k * CHK + tl) & (NSLOT - 1);
                float4 z0 = *(const float4*)&zbuf[s][lane][0];
                float4 z1 = *(const float4*)&zbuf[s][lane][4];
                float4 z2 = *(const float4*)&zbuf[s][lane][8];
                float4 z3 = *(const float4*)&zbuf[s][lane][12];

                float d[8][4];
                d[0][0] = z0.x; d[0][1] = z0.y; d[1][0] = z0.z; d[1][1] = z0.w;
                d[2][0] = z1.x; d[2][1] = z1.y; d[3][0] = z1.z; d[3][1] = z1.w;
                d[4][0] = z2.x; d[4][1] = z2.y; d[5][0] = z2.z; d[5][1] = z2.w;
                d[6][0] = z3.x; d[6][1] = z3.y; d[7][0] = z3.z; d[7][1] = z3.w;
#pragma unroll
                for (int nt = 0; nt < 8; nt++) { d[nt][2] = 0.0f; d[nt][3] = 0.0f; }

                uint32_t Ah[4] = {ah0, 0u, ah2, 0u};
                uint32_t Al[4] = {al0, 0u, al2, 0u};
#pragma unroll
                for (int nt = 0; nt < 8; nt++) {
                    mma16816(d[nt], Ah, bh[nt]);
                    mma16816(d[nt], Ah, bl[nt]);
                    mma16816(d[nt], Al, bh[nt]);
                }
                // gates: tiles 0,1 = i | 2,3 = f | 4,5 = g | 6,7 = o
                float i0 = fast_sigmoid(d[0][0]), i1 = fast_sigmoid(d[0][1]);
                float i2 = fast_sigmoid(d[1][0]), i3 = fast_sigmoid(d[1][1]);
                float f0 = fast_sigmoid(d[2][0]), f1 = fast_sigmoid(d[2][1]);
                float f2 = fast_sigmoid(d[3][0]), f3 = fast_sigmoid(d[3][1]);
                float g0 = fmaxf(d[4][0], 0.0f),  g1 = fmaxf(d[4][1], 0.0f);
                float g2 = fmaxf(d[5][0], 0.0f),  g3 = fmaxf(d[5][1], 0.0f);
                float o0 = fast_sigmoid(d[6][0]), o1 = fast_sigmoid(d[6][1]);
                float o2 = fast_sigmoid(d[7][0]), o3 = fast_sigmoid(d[7][1]);

                c0 = f0 * c0 + i0 * g0;  c1 = f1 * c1 + i1 * g1;
                c2 = f2 * c2 + i2 * g2;  c3 = f3 * c3 + i3 * g3;
                h0v = o0 * fmaxf(c0, 0.0f);  h1v = o1 * fmaxf(c1, 0.0f);
                h2v = o2 * fmaxf(c2, 0.0f);  h3v = o3 * fmaxf(c3, 0.0f);

                ah0 = bf16x2_hi(h0v, h1v);  al0 = bf16x2_lo(h0v, h1v, ah0);
                ah2 = bf16x2_hi(h2v, h3v);  al2 = bf16x2_lo(h2v, h3v, ah2);
            }
            BARRIER();
        }

        // ---- tail: gather h, run MLP head (8 lanes, one batch each) ----
        hbuf[gr][tq]     = h0v;
        hbuf[gr][tq + 1] = h1v;
        hbuf[gr][tq + 8] = h2v;
        hbuf[gr][tq + 9] = h3v;
        __syncwarp();
        if (lane < 8) {
            const float* hT = hbuf[lane];
            float x2v[8];
#pragma unroll
            for (int u = 0; u < 8; u++) {
                float s = __ldg(&b2[u]);
#pragma unroll
                for (int j = 0; j < 16; j++) s += hT[j] * __ldg(&W2[j * 8 + u]);
                x2v[u] = fmaxf(s, 0.0f);
            }
            float x3v[4];
#pragma unroll
            for (int u = 0; u < 4; u++) {
                float s = __ldg(&b3[u]);
#pragma unroll
                for (int j = 0; j < 8; j++) s += x2v[j] * __ldg(&W3[j * 4 + u]);
                x3v[u] = fmaxf(s, 0.0f);
            }
            float s = __ldg(&bo[0]);
#pragma unroll
            for (int u = 0; u < 4; u++) s += x3v[u] * __ldg(&Wo[u]);
            out[bg * 8 + lane] = fast_sigmoid(s);
        }
    }
}

extern "C" void kernel_launch(void* const* d_in, const int* in_sizes, int n_in,
                              void* d_out, int out_size) {
    (void)in_sizes; (void)n_in; (void)out_size;
    const float* x  = (const float*)d_in[0];
    const float* Wx = (const float*)d_in[1];
    const float* Wh = (const float*)d_in[2];
    const float* b  = (const float*)d_in[3];
    const float* W2 = (const float*)d_in[4];
    const float* b2 = (const float*)d_in[5];
    const float* W3 = (const float*)d_in[6];
    const float* b3 = (const float*)d_in[7];
    const float* Wo = (const float*)d_in[8];
    const float* bo = (const float*)d_in[9];
    float* out = (float*)d_out;

    prep_kernel<<<1, 128>>>(Wx);
    lstm_ws<<<Bsz / 8, 128>>>(x, Wh, b, W2, b2, W3, b3, Wo, bo, out);
}

// round 16
// speedup vs baseline: 1.0173x; 1.0173x over previous
#include <cuda_runtime.h>
#include <cuda_bf16.h>
#include <cstdint>

#define ULL unsigned long long

static constexpr int Bsz   = 2048;
static constexpr int T     = 512;
static constexpr int CHK   = 8;          // steps per chunk
static constexpr int NCHK  = T / CHK;    // 64
static constexpr int NSLOT = 16;         // ring slots (2 chunks)
static constexpr int ZP    = 66;         // ring pitch (floats); 264B rows -> 8B aligned

// pre-packed Wx B-fragments (bf16 hi/lo) + bias pairs
__device__ uint2  g_Bh[4][8][32];
__device__ uint2  g_Bl[4][8][32];
__device__ float2 g_bias[8][4];

// ---------------- helpers ----------------
__device__ __forceinline__ ULL f2pack(float lo, float hi) {
    ULL r; asm("mov.b64 %0, {%1, %2};" : "=l"(r) : "f"(lo), "f"(hi)); return r;
}
__device__ __forceinline__ void f2unpack(ULL v, float& lo, float& hi) {
    asm("mov.b64 {%0, %1}, %2;" : "=f"(lo), "=f"(hi) : "l"(v));
}
__device__ __forceinline__ ULL ffma2(ULL a, ULL b, ULL c) {
    ULL d; asm("fma.rn.f32x2 %0, %1, %2, %3;" : "=l"(d) : "l"(a), "l"(b), "l"(c)); return d;
}
__device__ __forceinline__ ULL fadd2(ULL a, ULL b) {
    ULL d; asm("add.rn.f32x2 %0, %1, %2;" : "=l"(d) : "l"(a), "l"(b)); return d;
}
__device__ __forceinline__ float fast_sigmoid(float x) {
    float e, r;
    asm("ex2.approx.f32 %0, %1;" : "=f"(e) : "f"(x * -1.4426950408889634f));
    asm("rcp.approx.f32 %0, %1;" : "=f"(r) : "f"(1.0f + e));
    return r;
}
__device__ __forceinline__ uint32_t bf16x2_hi(float x0, float x1) {
    uint32_t r; asm("cvt.rn.bf16x2.f32 %0, %1, %2;" : "=r"(r) : "f"(x1), "f"(x0)); return r;
}
__device__ __forceinline__ uint32_t bf16x2_lo(float x0, float x1, uint32_t hi) {
    float h0 = __uint_as_float(hi << 16);
    float h1 = __uint_as_float(hi & 0xFFFF0000u);
    return bf16x2_hi(x0 - h0, x1 - h1);
}
__device__ __forceinline__ void mma16816(float* c, const uint32_t* a, const uint32_t* b) {
    asm("mma.sync.aligned.m16n8k16.row.col.f32.bf16.bf16.f32 "
        "{%0,%1,%2,%3}, {%4,%5,%6,%7}, {%8,%9}, {%0,%1,%2,%3};"
        : "+f"(c[0]), "+f"(c[1]), "+f"(c[2]), "+f"(c[3])
        : "r"(a[0]), "r"(a[1]), "r"(a[2]), "r"(a[3]), "r"(b[0]), "r"(b[1]));
}
#define BAR() asm volatile("bar.sync 0, 384;" ::: "memory")

// ============================================================================
// prep: pack Wx into bf16 hi/lo B-fragments + bias pairs
// ============================================================================
__global__ void prep_kernel(const float* __restrict__ Wx, const float* __restrict__ bias) {
    const int tid  = threadIdx.x;
    const int ks   = tid >> 5;
    const int lane = tid & 31;
    const int gr   = lane >> 2;
    const int tq   = (lane & 3) * 2;
    const int k0   = ks * 16 + tq;
#pragma unroll
    for (int nt = 0; nt < 8; nt++) {
        const int n = nt * 8 + gr;
        float w00 = Wx[(k0)     * 64 + n], w01 = Wx[(k0 + 1) * 64 + n];
        float w10 = Wx[(k0 + 8) * 64 + n], w11 = Wx[(k0 + 9) * 64 + n];
        uint32_t h0 = bf16x2_hi(w00, w01);
        uint32_t h1 = bf16x2_hi(w10, w11);
        g_Bh[ks][nt][lane] = make_uint2(h0, h1);
        g_Bl[ks][nt][lane] = make_uint2(bf16x2_lo(w00, w01, h0), bf16x2_lo(w10, w11, h1));
    }
    if (tid < 32) {
        int nt = tid >> 2, q = tid & 3;
        g_bias[nt][q] = make_float2(bias[nt * 8 + 2 * q], bias[nt * 8 + 2 * q + 1]);
    }
}

// ============================================================================
// Warp-specialized fused LSTM. CTA = 12 warps, 8 batches:
//   warps 0-7 : consumers — one batch each, R5-rec chain, z from smem ring.
//   warps 8-11: producers — one per 2 batches; per 8-step chunk one m16n8k16
//               tile (rows = 2 batches x 8 steps), 96 MMAs -> ring.
// One bar.sync(0,384) per chunk; double-buffered 16-slot ring.
// ============================================================================
__global__ void __launch_bounds__(384, 2)
lstm_ws(const float* __restrict__ x,
        const float* __restrict__ Wh,   // [16, 64]
        const float* __restrict__ W2, const float* __restrict__ b2,
        const float* __restrict__ W3, const float* __restrict__ b3,
        const float* __restrict__ Wo, const float* __restrict__ bo,
        float* __restrict__ out)
{
    const int lane = threadIdx.x & 31;
    const int w    = threadIdx.x >> 5;       // 0..11
    const int bg   = blockIdx.x;             // 8 batches: bg*8 .. bg*8+7

    __shared__ __align__(16) float zr[NSLOT][8][ZP];   // 33.8 KB z ring
    __shared__ __align__(16) float sh[8][32];          // h per consumer warp

    if (w >= 8) {
        // ===================== PRODUCER (batches 2p, 2p+1) =====================
        const int p  = w - 8;
        const int gr = lane >> 2;
        const int tq = (lane & 3) * 2;
        const float* xb0 = x + (size_t)(bg * 8 + 2 * p)     * T * 64;
        const float* xb1 = x + (size_t)(bg * 8 + 2 * p + 1) * T * 64;

        auto produce = [&](int chunk) {
            const int t0 = chunk * CHK;
            // A-frag: row gr = (batch 2p, t0+gr); row gr+8 = (batch 2p+1, t0+gr)
            float2 ar[4][4];
#pragma unroll
            for (int ks = 0; ks < 4; ks++) {
                const int k0 = ks * 16 + tq;
                ar[ks][0] = *(const float2*)(xb0 + (size_t)(t0 + gr) * 64 + k0);
                ar[ks][1] = *(const float2*)(xb1 + (size_t)(t0 + gr) * 64 + k0);
                ar[ks][2] = *(const float2*)(xb0 + (size_t)(t0 + gr) * 64 + k0 + 8);
                ar[ks][3] = *(const float2*)(xb1 + (size_t)(t0 + gr) * 64 + k0 + 8);
            }
            uint32_t ah[4][4], al[4][4];
#pragma unroll
            for (int ks = 0; ks < 4; ks++)
#pragma unroll
                for (int j = 0; j < 4; j++) {
                    ah[ks][j] = bf16x2_hi(ar[ks][j].x, ar[ks][j].y);
                    al[ks][j] = bf16x2_lo(ar[ks][j].x, ar[ks][j].y, ah[ks][j]);
                }
            const int slot = (t0 + gr) & (NSLOT - 1);
#pragma unroll
            for (int nt = 0; nt < 8; nt++) {
                float chh[4] = {0, 0, 0, 0}, chl[4] = {0, 0, 0, 0}, clh[4] = {0, 0, 0, 0};
#pragma unroll
                for (int ks = 0; ks < 4; ks++) {
                    uint2 bh = __ldg(&g_Bh[ks][nt][lane]);
                    uint2 bl = __ldg(&g_Bl[ks][nt][lane]);
                    mma16816(chh, ah[ks], &bh.x);
                    mma16816(chl, ah[ks], &bl.x);
                    mma16816(clh, al[ks], &bh.x);
                }
                float2 bs = __ldg(&g_bias[nt][tq >> 1]);
                // D rows gr / gr+8 -> (batch 2p, t0+gr) / (batch 2p+1, t0+gr)
                *(float2*)&zr[slot][2 * p][nt * 8 + tq] =
                    make_float2(chh[0] + chl[0] + clh[0] + bs.x,
                                chh[1] + chl[1] + clh[1] + bs.y);
                *(float2*)&zr[slot][2 * p + 1][nt * 8 + tq] =
                    make_float2(chh[2] + chl[2] + clh[2] + bs.x,
                                chh[3] + chl[3] + clh[3] + bs.y);
            }
        };

        produce(0);
        BAR();
#pragma unroll 1
        for (int k = 0; k < NCHK; k++) {
            if (k + 1 < NCHK) produce(k + 1);
            BAR();
        }
    } else {
        // ===================== CONSUMER (batch bg*8 + w) =====================
        ULL wha[8], whb[8];
#pragma unroll
        for (int kk = 0; kk < 8; kk++) {
            wha[kk] = f2pack(__ldg(&Wh[(2 * kk) * 64 + lane]),
                             __ldg(&Wh[(2 * kk + 1) * 64 + lane]));
            whb[kk] = f2pack(__ldg(&Wh[(2 * kk) * 64 + lane + 32]),
                             __ldg(&Wh[(2 * kk + 1) * 64 + lane + 32]));
        }
        sh[w][lane] = 0.0f;
        float c_state = 0.0f;
        const ulonglong2* hv = (const ulonglong2*)sh[w];

        BAR();   // chunk 0 ready
#pragma unroll 1
        for (int k = 0; k < NCHK; k++) {
            const int tb = k * CHK;
            float zA = zr[tb & (NSLOT - 1)][w][lane];
            float zB = zr[tb & (NSLOT - 1)][w][lane + 32];
#pragma unroll
            for (int tl = 0; tl < CHK; tl++) {
                ULL hp[8];
                {
                    ulonglong2 v0 = hv[0], v1 = hv[1], v2 = hv[2], v3 = hv[3];
                    hp[0] = v0.x; hp[1] = v0.y; hp[2] = v1.x; hp[3] = v1.y;
                    hp[4] = v2.x; hp[5] = v2.y; hp[6] = v3.x; hp[7] = v3.y;
                }
                float zAn = 0.0f, zBn = 0.0f;
                if (tl + 1 < CHK) {                 // compile-time (unrolled)
                    const int s = (tb + tl + 1) & (NSLOT - 1);
                    zAn = zr[s][w][lane];
                    zBn = zr[s][w][lane + 32];
                }

                ULL aa0 = f2pack(zA, 0.0f), aa1 = 0ULL;
                ULL ab0 = f2pack(zB, 0.0f), ab1 = 0ULL;
#pragma unroll
                for (int kk = 0; kk < 8; kk++) {
                    if (kk & 1) { aa1 = ffma2(hp[kk], wha[kk], aa1); ab1 = ffma2(hp[kk], whb[kk], ab1); }
                    else        { aa0 = ffma2(hp[kk], wha[kk], aa0); ab0 = ffma2(hp[kk], whb[kk], ab0); }
                }
                ULL sa = fadd2(aa0, aa1), sb = fadd2(ab0, ab1);
                float a0, a1, b0, b1;
                f2unpack(sa, a0, a1);
                f2unpack(sb, b0, b1);
                float za  = a0 + a1;   // lane<16: i | lane>=16: f
                float zbv = b0 + b1;   // lane<16: g | lane>=16: o

                float v1 = fast_sigmoid(za);
                float v2 = (lane < 16) ? fmaxf(zbv, 0.0f) : fast_sigmoid(zbv);

                float fpart = __shfl_xor_sync(0xFFFFFFFFu, v1, 16);
                float opart = __shfl_xor_sync(0xFFFFFFFFu, v2, 16);

                c_state = fpart * c_state + v1 * v2;      // valid lanes 0..15
                float hnew = opart * fmaxf(c_state, 0.0f);
                sh[w][lane] = hnew;
                __syncwarp();

                zA = zAn; zB = zBn;
            }
            BAR();
        }

        // ---- MLP head: lane 0 per consumer warp ----
        if (lane == 0) {
            const float* hT = sh[w];
            float x2v[8];
#pragma unroll
            for (int u = 0; u < 8; u++) {
                float s = __ldg(&b2[u]);
#pragma unroll
                for (int j = 0; j < 16; j++) s += hT[j] * __ldg(&W2[j * 8 + u]);
                x2v[u] = fmaxf(s, 0.0f);
            }
            float x3v[4];
#pragma unroll
            for (int u = 0; u < 4; u++) {
                float s = __ldg(&b3[u]);
#pragma unroll
                for (int j = 0; j < 8; j++) s += x2v[j] * __ldg(&W3[j * 4 + u]);
                x3v[u] = fmaxf(s, 0.0f);
            }
            float s = __ldg(&bo[0]);
#pragma unroll
            for (int u = 0; u < 4; u++) s += x3v[u] * __ldg(&Wo[u]);
            out[bg * 8 + w] = fast_sigmoid(s);
        }
    }
}

extern "C" void kernel_launch(void* const* d_in, const int* in_sizes, int n_in,
                              void* d_out, int out_size) {
    (void)in_sizes; (void)n_in; (void)out_size;
    const float* x  = (const float*)d_in[0];
    const float* Wx = (const float*)d_in[1];
    const float* Wh = (const float*)d_in[2];
    const float* b  = (const float*)d_in[3];
    const float* W2 = (const float*)d_in[4];
    const float* b2 = (const float*)d_in[5];
    const float* W3 = (const float*)d_in[6];
    const float* b3 = (const float*)d_in[7];
    const float* Wo = (const float*)d_in[8];
    const float* bo = (const float*)d_in[9];
    float* out = (float*)d_out;

    prep_kernel<<<1, 128>>>(Wx, b);
    lstm_ws<<<Bsz / 8, 384>>>(x, Wh, W2, b2, W3, b3, Wo, bo, out);
}